// round 7
// baseline (speedup 1.0000x reference)
#include <cuda_runtime.h>
#include <cuda_bf16.h>
#include <cstddef>

// Problem constants
#define NUM_C 1000
#define Dd    128
#define Mm    64
#define Bb    64
#define Ll    512
#define NROWS (Bb * Ll)   // 32768
#define CH    16          // scan: steps staged per chunk

typedef unsigned long long u64;

// Scratch (static device globals — allocation-free)
__device__ float g_w[NROWS * Mm];
__device__ float g_e[NROWS * Dd];
__device__ float g_a[NROWS * Dd];
__device__ float g_read[NROWS * Dd];
__device__ u64   g_WfP [(Dd / 2) * Dd];   // (Wf[2jp][c], Wf[2jp+1][c])
__device__ u64   g_WfkP[(Dd / 2) * Dd];   // (Wf[Dd+2jp][c], Wf[Dd+2jp+1][c])

__device__ __forceinline__ float sigmoidf_(float x) {
    return 1.0f / (1.0f + __expf(-x));
}
__device__ __forceinline__ u64 bcast2(float x) {
    u64 r; asm("mov.b64 %0, {%1,%1};" : "=l"(r) : "f"(x)); return r;
}
__device__ __forceinline__ u64 pack2(float x, float y) {
    u64 r; asm("mov.b64 %0, {%1,%2};" : "=l"(r) : "f"(x), "f"(y)); return r;
}
__device__ __forceinline__ u64 fma2(u64 a, u64 b, u64 c) {
    u64 d; asm("fma.rn.f32x2 %0, %1, %2, %3;" : "=l"(d) : "l"(a), "l"(b), "l"(c)); return d;
}
__device__ __forceinline__ float2 unpk(u64 v) {
    float2 f; asm("mov.b64 {%0,%1}, %2;" : "=f"(f.x), "=f"(f.y) : "l"(v)); return f;
}
__device__ __forceinline__ float hsum2(u64 v) {
    float2 f = unpk(v); return f.x + f.y;
}

// ---------------------------------------------------------------------------
// Kernel 0: repack Wf into j-pair-major u64 layout (both halves).
// ---------------------------------------------------------------------------
__global__ __launch_bounds__(256) void k_prep(const float* __restrict__ Wf)
{
    int idx = blockIdx.x * 256 + threadIdx.x;      // 0 .. 8191
    if (idx < (Dd / 2) * Dd) {
        int jp = idx >> 7;        // 0..63
        int c  = idx & 127;
        g_WfP [idx] = pack2(Wf[(size_t)(2 * jp)     * Dd + c], Wf[(size_t)(2 * jp + 1)     * Dd + c]);
        g_WfkP[idx] = pack2(Wf[(size_t)(Dd + 2 * jp) * Dd + c], Wf[(size_t)(Dd + 2 * jp + 1) * Dd + c]);
    }
}

// ---------------------------------------------------------------------------
// Kernel 1a: logits + softmax -> w.   512 threads, 64 rows/block.
// ---------------------------------------------------------------------------
__global__ __launch_bounds__(512, 2) void k_w(
    const int* __restrict__ q,
    const float* __restrict__ Ek,
    const float* __restrict__ Mk)
{
    extern __shared__ float sm[];
    float* sK   = sm;                 // [64][Dd]  32 KB
    float* sMkP = sm + 64 * Dd;       // [64 jp][64 slots float2]  32 KB

    const int tid  = threadIdx.x;
    const int row0 = blockIdx.x * 64;

    for (int i = tid; i < 64 * (Dd / 4); i += 512) {
        int rr = i >> 5;
        int c4 = i & 31;
        int qi = q[row0 + rr];
        ((float4*)(sK + rr * Dd))[c4] = ((const float4*)(Ek + (size_t)qi * Dd))[c4];
    }
    for (int i = tid; i < Mm * (Dd / 2); i += 512) {
        int s  = i & 63;
        int jp = i >> 6;
        ((float2*)sMkP)[jp * 64 + s] = *(const float2*)(Mk + (size_t)s * Dd + 2 * jp);
    }
    __syncthreads();

    const int wid = tid >> 5;
    const int cg  = tid & 31;

    u64 acc0[4], acc1[4];
    #pragma unroll
    for (int i = 0; i < 4; i++) { acc0[i] = 0ull; acc1[i] = 0ull; }

    for (int jp = 0; jp < Dd / 2; jp++) {
        ulonglong2 mk2 = ((const ulonglong2*)(sMkP + jp * 128))[cg];
        #pragma unroll
        for (int i = 0; i < 4; i++) {
            u64 k2 = *(const u64*)(sK + (wid * 4 + i) * Dd + 2 * jp);
            acc0[i] = fma2(k2, mk2.x, acc0[i]);
            acc1[i] = fma2(k2, mk2.y, acc1[i]);
        }
    }
    #pragma unroll
    for (int i = 0; i < 4; i++) {
        float l0 = hsum2(acc0[i]);
        float l1 = hsum2(acc1[i]);
        float mx = fmaxf(l0, l1);
        #pragma unroll
        for (int o = 16; o > 0; o >>= 1)
            mx = fmaxf(mx, __shfl_xor_sync(0xffffffffu, mx, o));
        float e0 = __expf(l0 - mx);
        float e1 = __expf(l1 - mx);
        float s = e0 + e1;
        #pragma unroll
        for (int o = 16; o > 0; o >>= 1)
            s += __shfl_xor_sync(0xffffffffu, s, o);
        float inv = 1.0f / s;
        *(float2*)(g_w + (size_t)(row0 + wid * 4 + i) * Mm + 2 * cg) =
            make_float2(e0 * inv, e1 * inv);
    }
}

// ---------------------------------------------------------------------------
// Kernel 1b: e = sigmoid(v We + be), a = tanh(v Wa + ba).
// 256 threads, 32 rows/block; weights loaded as ulonglong2 (no packing movs).
// ---------------------------------------------------------------------------
__global__ __launch_bounds__(256, 4) void k_ea(
    const int* __restrict__ q, const int* __restrict__ r,
    const float* __restrict__ Ev,
    const float* __restrict__ We, const float* __restrict__ be,
    const float* __restrict__ Wa, const float* __restrict__ ba)
{
    extern __shared__ float sm[];
    float* sV = sm;   // [32][Dd]  16 KB

    const int tid  = threadIdx.x;
    const int row0 = blockIdx.x * 32;

    for (int i = tid; i < 32 * (Dd / 4); i += 256) {
        int rr = i >> 5;
        int c4 = i & 31;
        int gr = row0 + rr;
        int xi = q[gr] + NUM_C * r[gr];
        ((float4*)(sV + rr * Dd))[c4] = ((const float4*)(Ev + (size_t)xi * Dd))[c4];
    }
    __syncthreads();

    const int wid = tid >> 5;
    const int cg  = tid & 31;

    u64 eA[4], eB[4], aA[4], aB[4];
    #pragma unroll
    for (int i = 0; i < 4; i++) { eA[i]=0ull; eB[i]=0ull; aA[i]=0ull; aB[i]=0ull; }

    for (int j = 0; j < Dd; j++) {
        ulonglong2 we = ((const ulonglong2*)(We + (size_t)j * Dd))[cg];
        ulonglong2 wa = ((const ulonglong2*)(Wa + (size_t)j * Dd))[cg];
        #pragma unroll
        for (int i = 0; i < 4; i++) {
            u64 b0 = bcast2(sV[(wid * 4 + i) * Dd + j]);
            eA[i] = fma2(b0, we.x, eA[i]);
            eB[i] = fma2(b0, we.y, eB[i]);
            aA[i] = fma2(b0, wa.x, aA[i]);
            aB[i] = fma2(b0, wa.y, aB[i]);
        }
    }

    float4 bev = ((const float4*)be)[cg];
    float4 bav = ((const float4*)ba)[cg];
    #pragma unroll
    for (int i = 0; i < 4; i++) {
        size_t row = (size_t)(row0 + wid * 4 + i);
        float2 ea = unpk(eA[i]), eb = unpk(eB[i]);
        float2 aa = unpk(aA[i]), ab = unpk(aB[i]);
        float4 ev, av;
        ev.x = sigmoidf_(ea.x + bev.x);
        ev.y = sigmoidf_(ea.y + bev.y);
        ev.z = sigmoidf_(eb.x + bev.z);
        ev.w = sigmoidf_(eb.y + bev.w);
        av.x = tanhf(aa.x + bav.x);
        av.y = tanhf(aa.y + bav.y);
        av.z = tanhf(ab.x + bav.z);
        av.w = tanhf(ab.y + bav.w);
        ((float4*)(g_e + row * Dd))[cg] = ev;
        ((float4*)(g_a + row * Dd))[cg] = av;
    }
}

// ---------------------------------------------------------------------------
// Kernel 2: sequential memory scan. grid (64 batches, 4 d-quarters), 256 thr.
// ---------------------------------------------------------------------------
__global__ __launch_bounds__(256) void k_scan(const float* __restrict__ Mv0)
{
    const int b    = blockIdx.x;
    const int qtr  = blockIdx.y;
    const int tid  = threadIdx.x;
    const int mg   = tid & 7;
    const int dl   = tid >> 3;          // 0..31
    const int d    = qtr * 32 + dl;

    float Mv[8];
    #pragma unroll
    for (int i = 0; i < 8; i++)
        Mv[i] = Mv0[(mg * 8 + i) * Dd + d];

    __shared__ float sW[CH][Mm];
    __shared__ float sE[CH][32];
    __shared__ float sA[CH][32];

    const size_t rbase = (size_t)b * Ll;

    for (int c = 0; c < Ll / CH; c++) {
        __syncthreads();
        ((float4*)sW)[tid] = ((const float4*)(g_w + (rbase + (size_t)c * CH) * Mm))[tid];
        {
            int t2 = tid & 127;
            int tt = t2 >> 3;
            int c4 = t2 & 7;
            size_t row = rbase + (size_t)c * CH + tt;
            if (tid < 128)
                ((float4*)(sE[tt]))[c4] = ((const float4*)(g_e + row * Dd + qtr * 32))[c4];
            else
                ((float4*)(sA[tt]))[c4] = ((const float4*)(g_a + row * Dd + qtr * 32))[c4];
        }
        __syncthreads();

        #pragma unroll 4
        for (int tt = 0; tt < CH; tt++) {
            float ed = sE[tt][dl];
            float ad = sA[tt][dl];
            float rp0 = 0.f, rp1 = 0.f, rp2 = 0.f, rp3 = 0.f;

            float4 w0 = ((const float4*)(sW[tt] + mg * 8))[0];
            float4 w1 = ((const float4*)(sW[tt] + mg * 8))[1];

            #define STEP(W, RP, IDX) do {                         \
                RP = fmaf(W, Mv[IDX], RP);                        \
                float t_ = fmaf(Mv[IDX], ed, -ad);                \
                Mv[IDX] = fmaf(-(W), t_, Mv[IDX]);                \
            } while (0)

            STEP(w0.x, rp0, 0);  STEP(w0.y, rp1, 1);
            STEP(w0.z, rp2, 2);  STEP(w0.w, rp3, 3);
            STEP(w1.x, rp0, 4);  STEP(w1.y, rp1, 5);
            STEP(w1.z, rp2, 6);  STEP(w1.w, rp3, 7);
            #undef STEP

            float rp = (rp0 + rp1) + (rp2 + rp3);
            rp += __shfl_xor_sync(0xffffffffu, rp, 1);
            rp += __shfl_xor_sync(0xffffffffu, rp, 2);
            rp += __shfl_xor_sync(0xffffffffu, rp, 4);
            if (mg == 0)
                g_read[(rbase + (size_t)c * CH + tt) * Dd + d] = rp;
        }
    }
}

// ---------------------------------------------------------------------------
// Kernel 3: f = tanh([read | k] @ Wf + bf); p = sigmoid(f . Wp + bp)
// j-pair packed weights from g_WfP / g_WfkP — zero packing movs in loop.
// ---------------------------------------------------------------------------
__global__ __launch_bounds__(256, 4) void k_post(
    const int* __restrict__ q,
    const float* __restrict__ Ek,
    const float* __restrict__ bf,
    const float* __restrict__ Wp, const float* __restrict__ bp,
    float* __restrict__ out)
{
    extern __shared__ float sm[];
    float* sR = sm;             // [32][Dd]
    float* sK = sm + 32 * Dd;   // [32][Dd]

    const int tid  = threadIdx.x;
    const int row0 = blockIdx.x * 32;

    for (int i = tid; i < 32 * (Dd / 4); i += 256) {
        int rr = i >> 5;
        int c4 = i & 31;
        int gr = row0 + rr;
        int qi = q[gr];
        ((float4*)(sK + rr * Dd))[c4] = ((const float4*)(Ek + (size_t)qi * Dd))[c4];
        ((float4*)(sR + rr * Dd))[c4] = ((const float4*)(g_read + (size_t)gr * Dd))[c4];
    }
    __syncthreads();

    const int wid = tid >> 5;
    const int cg  = tid & 31;

    u64 ac0[4], ac1[4], ac2[4], ac3[4];
    #pragma unroll
    for (int i = 0; i < 4; i++) { ac0[i]=0ull; ac1[i]=0ull; ac2[i]=0ull; ac3[i]=0ull; }

    for (int jp = 0; jp < Dd / 2; jp++) {
        ulonglong2 wr01 = ((const ulonglong2*)(g_WfP  + jp * Dd))[2 * cg];
        ulonglong2 wr23 = ((const ulonglong2*)(g_WfP  + jp * Dd))[2 * cg + 1];
        ulonglong2 wk01 = ((const ulonglong2*)(g_WfkP + jp * Dd))[2 * cg];
        ulonglong2 wk23 = ((const ulonglong2*)(g_WfkP + jp * Dd))[2 * cg + 1];
        #pragma unroll
        for (int i = 0; i < 4; i++) {
            u64 rj2 = *(const u64*)(sR + (wid * 4 + i) * Dd + 2 * jp);
            u64 kj2 = *(const u64*)(sK + (wid * 4 + i) * Dd + 2 * jp);
            ac0[i] = fma2(rj2, wr01.x, ac0[i]);
            ac1[i] = fma2(rj2, wr01.y, ac1[i]);
            ac2[i] = fma2(rj2, wr23.x, ac2[i]);
            ac3[i] = fma2(rj2, wr23.y, ac3[i]);
            ac0[i] = fma2(kj2, wk01.x, ac0[i]);
            ac1[i] = fma2(kj2, wk01.y, ac1[i]);
            ac2[i] = fma2(kj2, wk23.x, ac2[i]);
            ac3[i] = fma2(kj2, wk23.y, ac3[i]);
        }
    }

    float4 bfv = ((const float4*)bf)[cg];
    float4 wp4 = ((const float4*)Wp)[cg];
    float bpv  = bp[0];

    #pragma unroll
    for (int i = 0; i < 4; i++) {
        float fx = tanhf(hsum2(ac0[i]) + bfv.x);
        float fy = tanhf(hsum2(ac1[i]) + bfv.y);
        float fz = tanhf(hsum2(ac2[i]) + bfv.z);
        float fw = tanhf(hsum2(ac3[i]) + bfv.w);
        float pp = fx * wp4.x + fy * wp4.y + fz * wp4.z + fw * wp4.w;
        #pragma unroll
        for (int o = 16; o > 0; o >>= 1)
            pp += __shfl_xor_sync(0xffffffffu, pp, o);
        if (cg == 0)
            out[row0 + wid * 4 + i] = sigmoidf_(pp + bpv);
    }
}

// ---------------------------------------------------------------------------
extern "C" void kernel_launch(void* const* d_in, const int* in_sizes, int n_in,
                              void* d_out, int out_size)
{
    const int*   q   = (const int*)  d_in[0];
    const int*   r   = (const int*)  d_in[1];
    const float* Ek  = (const float*)d_in[2];
    const float* Ev  = (const float*)d_in[3];
    const float* Mk  = (const float*)d_in[4];
    const float* Mv0 = (const float*)d_in[5];
    const float* We  = (const float*)d_in[6];
    const float* be  = (const float*)d_in[7];
    const float* Wa  = (const float*)d_in[8];
    const float* ba  = (const float*)d_in[9];
    const float* Wf  = (const float*)d_in[10];
    const float* bf  = (const float*)d_in[11];
    const float* Wp  = (const float*)d_in[12];
    const float* bp  = (const float*)d_in[13];
    float* out = (float*)d_out;

    const size_t smW  = (size_t)(64 * Dd + (Dd / 2) * Mm * 2) * sizeof(float); // 65536 B
    const size_t smEA = (size_t)(32 * Dd) * sizeof(float);                     // 16384 B
    const size_t smP  = (size_t)(2 * 32 * Dd) * sizeof(float);                 // 32768 B
    cudaFuncSetAttribute(k_w,    cudaFuncAttributeMaxDynamicSharedMemorySize, (int)smW);
    cudaFuncSetAttribute(k_ea,   cudaFuncAttributeMaxDynamicSharedMemorySize, (int)smEA);
    cudaFuncSetAttribute(k_post, cudaFuncAttributeMaxDynamicSharedMemorySize, (int)smP);

    k_prep<<<32, 256>>>(Wf);
    k_w   <<<NROWS / 64, 512, smW>>>(q, Ek, Mk);
    k_ea  <<<NROWS / 32, 256, smEA>>>(q, r, Ev, We, be, Wa, ba);
    k_scan<<<dim3(Bb, 4), 256>>>(Mv0);
    k_post<<<NROWS / 32, 256, smP>>>(q, Ek, bf, Wp, bp, out);
}

// round 9
// speedup vs baseline: 1.0171x; 1.0171x over previous
#include <cuda_runtime.h>
#include <cuda_bf16.h>
#include <cstddef>

// Problem constants
#define NUM_C 1000
#define Dd    128
#define Mm    64
#define Bb    64
#define Ll    512
#define NROWS (Bb * Ll)   // 32768
#define CC    64          // scan chunk length
#define NCH   (Ll / CC)   // 8 chunks

typedef unsigned long long u64;

// Scratch (static device globals — allocation-free)
__device__ float g_w[NROWS * Mm];
__device__ float g_e[NROWS * Dd];
__device__ float g_a[NROWS * Dd];
__device__ float g_read[NROWS * Dd];
// chunked-scan summaries / states: [b][chunk][m][d]
__device__ float g_A[Bb * NCH * Mm * Dd];
__device__ float g_B[Bb * NCH * Mm * Dd];
__device__ float g_S[Bb * NCH * Mm * Dd];

__device__ __forceinline__ float sigmoidf_(float x) {
    return 1.0f / (1.0f + __expf(-x));
}
__device__ __forceinline__ u64 bcast2(float x) {
    u64 r; asm("mov.b64 %0, {%1,%1};" : "=l"(r) : "f"(x)); return r;
}
__device__ __forceinline__ u64 pack2(float x, float y) {
    u64 r; asm("mov.b64 %0, {%1,%2};" : "=l"(r) : "f"(x), "f"(y)); return r;
}
__device__ __forceinline__ u64 fma2(u64 a, u64 b, u64 c) {
    u64 d; asm("fma.rn.f32x2 %0, %1, %2, %3;" : "=l"(d) : "l"(a), "l"(b), "l"(c)); return d;
}
__device__ __forceinline__ float2 unpk(u64 v) {
    float2 f; asm("mov.b64 {%0,%1}, %2;" : "=f"(f.x), "=f"(f.y) : "l"(v)); return f;
}
__device__ __forceinline__ float hsum2(u64 v) {
    float2 f = unpk(v); return f.x + f.y;
}

// ---------------------------------------------------------------------------
// Kernel 1a: logits + softmax -> w.   512 threads, 64 rows/block.
// ---------------------------------------------------------------------------
__global__ __launch_bounds__(512, 2) void k_w(
    const int* __restrict__ q,
    const float* __restrict__ Ek,
    const float* __restrict__ Mk)
{
    extern __shared__ float sm[];
    float* sK   = sm;                 // [64][Dd]  32 KB
    float* sMkP = sm + 64 * Dd;       // [64 jp][64 slots float2]  32 KB

    const int tid  = threadIdx.x;
    const int row0 = blockIdx.x * 64;

    for (int i = tid; i < 64 * (Dd / 4); i += 512) {
        int rr = i >> 5;
        int c4 = i & 31;
        int qi = q[row0 + rr];
        ((float4*)(sK + rr * Dd))[c4] = ((const float4*)(Ek + (size_t)qi * Dd))[c4];
    }
    for (int i = tid; i < Mm * (Dd / 2); i += 512) {
        int s  = i & 63;
        int jp = i >> 6;
        ((float2*)sMkP)[jp * 64 + s] = *(const float2*)(Mk + (size_t)s * Dd + 2 * jp);
    }
    __syncthreads();

    const int wid = tid >> 5;
    const int cg  = tid & 31;

    u64 acc0[4], acc1[4];
    #pragma unroll
    for (int i = 0; i < 4; i++) { acc0[i] = 0ull; acc1[i] = 0ull; }

    for (int jp = 0; jp < Dd / 2; jp++) {
        ulonglong2 mk2 = ((const ulonglong2*)(sMkP + jp * 128))[cg];
        #pragma unroll
        for (int i = 0; i < 4; i++) {
            u64 k2 = *(const u64*)(sK + (wid * 4 + i) * Dd + 2 * jp);
            acc0[i] = fma2(k2, mk2.x, acc0[i]);
            acc1[i] = fma2(k2, mk2.y, acc1[i]);
        }
    }
    #pragma unroll
    for (int i = 0; i < 4; i++) {
        float l0 = hsum2(acc0[i]);
        float l1 = hsum2(acc1[i]);
        float mx = fmaxf(l0, l1);
        #pragma unroll
        for (int o = 16; o > 0; o >>= 1)
            mx = fmaxf(mx, __shfl_xor_sync(0xffffffffu, mx, o));
        float e0 = __expf(l0 - mx);
        float e1 = __expf(l1 - mx);
        float s = e0 + e1;
        #pragma unroll
        for (int o = 16; o > 0; o >>= 1)
            s += __shfl_xor_sync(0xffffffffu, s, o);
        float inv = 1.0f / s;
        *(float2*)(g_w + (size_t)(row0 + wid * 4 + i) * Mm + 2 * cg) =
            make_float2(e0 * inv, e1 * inv);
    }
}

// ---------------------------------------------------------------------------
// Kernel 1b: e = sigmoid(v We + be), a = tanh(v Wa + ba).
// ---------------------------------------------------------------------------
__global__ __launch_bounds__(256, 4) void k_ea(
    const int* __restrict__ q, const int* __restrict__ r,
    const float* __restrict__ Ev,
    const float* __restrict__ We, const float* __restrict__ be,
    const float* __restrict__ Wa, const float* __restrict__ ba)
{
    extern __shared__ float sm[];
    float* sV = sm;   // [32][Dd]  16 KB

    const int tid  = threadIdx.x;
    const int row0 = blockIdx.x * 32;

    for (int i = tid; i < 32 * (Dd / 4); i += 256) {
        int rr = i >> 5;
        int c4 = i & 31;
        int gr = row0 + rr;
        int xi = q[gr] + NUM_C * r[gr];
        ((float4*)(sV + rr * Dd))[c4] = ((const float4*)(Ev + (size_t)xi * Dd))[c4];
    }
    __syncthreads();

    const int wid = tid >> 5;
    const int cg  = tid & 31;

    u64 eA[4], eB[4], aA[4], aB[4];
    #pragma unroll
    for (int i = 0; i < 4; i++) { eA[i]=0ull; eB[i]=0ull; aA[i]=0ull; aB[i]=0ull; }

    for (int j = 0; j < Dd; j++) {
        float4 we = ((const float4*)(We + (size_t)j * Dd))[cg];
        float4 wa = ((const float4*)(Wa + (size_t)j * Dd))[cg];
        u64 weA = pack2(we.x, we.y), weB = pack2(we.z, we.w);
        u64 waA = pack2(wa.x, wa.y), waB = pack2(wa.z, wa.w);
        #pragma unroll
        for (int i = 0; i < 4; i++) {
            u64 b0 = bcast2(sV[(wid * 4 + i) * Dd + j]);
            eA[i] = fma2(b0, weA, eA[i]);
            eB[i] = fma2(b0, weB, eB[i]);
            aA[i] = fma2(b0, waA, aA[i]);
            aB[i] = fma2(b0, waB, aB[i]);
        }
    }

    float4 bev = ((const float4*)be)[cg];
    float4 bav = ((const float4*)ba)[cg];
    #pragma unroll
    for (int i = 0; i < 4; i++) {
        size_t row = (size_t)(row0 + wid * 4 + i);
        float2 ea = unpk(eA[i]), eb = unpk(eB[i]);
        float2 aa = unpk(aA[i]), ab = unpk(aB[i]);
        float4 ev, av;
        ev.x = sigmoidf_(ea.x + bev.x);
        ev.y = sigmoidf_(ea.y + bev.y);
        ev.z = sigmoidf_(eb.x + bev.z);
        ev.w = sigmoidf_(eb.y + bev.w);
        av.x = tanhf(aa.x + bav.x);
        av.y = tanhf(aa.y + bav.y);
        av.z = tanhf(ab.x + bav.z);
        av.w = tanhf(ab.y + bav.w);
        ((float4*)(g_e + row * Dd))[cg] = ev;
        ((float4*)(g_a + row * Dd))[cg] = av;
    }
}

// ---------------------------------------------------------------------------
// Scan pass 1: per-chunk affine composition.  grid (64 b, 8 c, 2 halves).
// dl = tid>>2 owns one d (within half); mg = tid&3 owns 16 m-rows.
// A = prod alpha, B = affine offset, where alpha = 1 - w*e, beta = w*a.
// ---------------------------------------------------------------------------
__global__ __launch_bounds__(256) void k_scan1()
{
    extern __shared__ float sm[];
    float* sW = sm;              // [CC][64]
    float* sE = sm + CC * 64;    // [CC][64]
    float* sA = sm + 2 * CC * 64;

    const int b    = blockIdx.x;
    const int c    = blockIdx.y;
    const int half = blockIdx.z;
    const int tid  = threadIdx.x;

    const size_t row0 = (size_t)b * Ll + (size_t)c * CC;

    // stage w: CC*64 floats = 1024 float4
    #pragma unroll
    for (int k = 0; k < 4; k++)
        ((float4*)sW)[tid + k * 256] = ((const float4*)(g_w + row0 * Mm))[tid + k * 256];
    // stage e, a: CC rows x 16 float4 each
    #pragma unroll
    for (int k = 0; k < 4; k++) {
        int i  = tid + k * 256;
        int t  = i >> 4;
        int c4 = i & 15;
        ((float4*)(sE + t * 64))[c4] = ((const float4*)(g_e + (row0 + t) * Dd + half * 64))[c4];
        ((float4*)(sA + t * 64))[c4] = ((const float4*)(g_a + (row0 + t) * Dd + half * 64))[c4];
    }
    __syncthreads();

    const int dl = tid >> 2;
    const int mg = tid & 3;

    float Af[16], Bf[16];
    #pragma unroll
    for (int i = 0; i < 16; i++) { Af[i] = 1.0f; Bf[i] = 0.0f; }

    for (int t = 0; t < CC; t++) {
        float ed = sE[t * 64 + dl];
        float ad = sA[t * 64 + dl];
        float4 w0 = ((const float4*)(sW + t * 64 + mg * 16))[0];
        float4 w1 = ((const float4*)(sW + t * 64 + mg * 16))[1];
        float4 w2 = ((const float4*)(sW + t * 64 + mg * 16))[2];
        float4 w3 = ((const float4*)(sW + t * 64 + mg * 16))[3];

        #define CSTEP(W, IDX) do {                        \
            float al = fmaf(-(W), ed, 1.0f);              \
            Bf[IDX] = fmaf(al, Bf[IDX], (W) * ad);        \
            Af[IDX] *= al;                                \
        } while (0)
        CSTEP(w0.x, 0);  CSTEP(w0.y, 1);  CSTEP(w0.z, 2);  CSTEP(w0.w, 3);
        CSTEP(w1.x, 4);  CSTEP(w1.y, 5);  CSTEP(w1.z, 6);  CSTEP(w1.w, 7);
        CSTEP(w2.x, 8);  CSTEP(w2.y, 9);  CSTEP(w2.z, 10); CSTEP(w2.w, 11);
        CSTEP(w3.x, 12); CSTEP(w3.y, 13); CSTEP(w3.z, 14); CSTEP(w3.w, 15);
        #undef CSTEP
    }

    const size_t base = ((size_t)(b * NCH + c) * Mm + mg * 16) * Dd + half * 64 + dl;
    #pragma unroll
    for (int i = 0; i < 16; i++) {
        g_A[base + (size_t)i * Dd] = Af[i];
        g_B[base + (size_t)i * Dd] = Bf[i];
    }
}

// ---------------------------------------------------------------------------
// Scan pass 2: prefix across chunks; store each chunk's START state.
// 512K independent (m,d,b) cells.  grid (64, 32), 256 threads.
// ---------------------------------------------------------------------------
__global__ __launch_bounds__(256) void k_scan2(const float* __restrict__ Mv0)
{
    const int b    = blockIdx.x;
    const int cell = blockIdx.y * 256 + threadIdx.x;   // 0..8191 = m*128 + d

    float S = Mv0[cell];
    #pragma unroll
    for (int c = 0; c < NCH; c++) {
        size_t idx = (size_t)(b * NCH + c) * (Mm * Dd) + cell;
        g_S[idx] = S;
        S = fmaf(g_A[idx], S, g_B[idx]);
    }
}

// ---------------------------------------------------------------------------
// Scan pass 3: replay chunk from start state; emit reads.
// grid (64 b, 8 c, 2 halves), 256 threads; same layout as pass 1.
// ---------------------------------------------------------------------------
__global__ __launch_bounds__(256) void k_scan3()
{
    extern __shared__ float sm[];
    float* sW = sm;
    float* sE = sm + CC * 64;
    float* sA = sm + 2 * CC * 64;

    const int b    = blockIdx.x;
    const int c    = blockIdx.y;
    const int half = blockIdx.z;
    const int tid  = threadIdx.x;

    const size_t row0 = (size_t)b * Ll + (size_t)c * CC;

    #pragma unroll
    for (int k = 0; k < 4; k++)
        ((float4*)sW)[tid + k * 256] = ((const float4*)(g_w + row0 * Mm))[tid + k * 256];
    #pragma unroll
    for (int k = 0; k < 4; k++) {
        int i  = tid + k * 256;
        int t  = i >> 4;
        int c4 = i & 15;
        ((float4*)(sE + t * 64))[c4] = ((const float4*)(g_e + (row0 + t) * Dd + half * 64))[c4];
        ((float4*)(sA + t * 64))[c4] = ((const float4*)(g_a + (row0 + t) * Dd + half * 64))[c4];
    }
    __syncthreads();

    const int dl = tid >> 2;
    const int mg = tid & 3;
    const int d  = half * 64 + dl;

    float Mv[16];
    {
        const size_t base = ((size_t)(b * NCH + c) * Mm + mg * 16) * Dd + d;
        #pragma unroll
        for (int i = 0; i < 16; i++)
            Mv[i] = g_S[base + (size_t)i * Dd];
    }

    for (int t = 0; t < CC; t++) {
        float ed = sE[t * 64 + dl];
        float ad = sA[t * 64 + dl];
        float rp0 = 0.f, rp1 = 0.f, rp2 = 0.f, rp3 = 0.f;

        float4 w0 = ((const float4*)(sW + t * 64 + mg * 16))[0];
        float4 w1 = ((const float4*)(sW + t * 64 + mg * 16))[1];
        float4 w2 = ((const float4*)(sW + t * 64 + mg * 16))[2];
        float4 w3 = ((const float4*)(sW + t * 64 + mg * 16))[3];

        #define STEP(W, RP, IDX) do {                     \
            RP = fmaf(W, Mv[IDX], RP);                    \
            float t_ = fmaf(Mv[IDX], ed, -ad);            \
            Mv[IDX] = fmaf(-(W), t_, Mv[IDX]);            \
        } while (0)
        STEP(w0.x, rp0, 0);  STEP(w0.y, rp1, 1);  STEP(w0.z, rp2, 2);  STEP(w0.w, rp3, 3);
        STEP(w1.x, rp0, 4);  STEP(w1.y, rp1, 5);  STEP(w1.z, rp2, 6);  STEP(w1.w, rp3, 7);
        STEP(w2.x, rp0, 8);  STEP(w2.y, rp1, 9);  STEP(w2.z, rp2, 10); STEP(w2.w, rp3, 11);
        STEP(w3.x, rp0, 12); STEP(w3.y, rp1, 13); STEP(w3.z, rp2, 14); STEP(w3.w, rp3, 15);
        #undef STEP

        float rp = (rp0 + rp1) + (rp2 + rp3);
        rp += __shfl_xor_sync(0xffffffffu, rp, 1);
        rp += __shfl_xor_sync(0xffffffffu, rp, 2);
        if (mg == 0)
            g_read[(row0 + t) * Dd + d] = rp;
    }
}

// ---------------------------------------------------------------------------
// Kernel 3: f = tanh([read | k] @ Wf + bf); p = sigmoid(f . Wp + bp)
// ---------------------------------------------------------------------------
__global__ __launch_bounds__(256, 4) void k_post(
    const int* __restrict__ q,
    const float* __restrict__ Ek,
    const float* __restrict__ Wf, const float* __restrict__ bf,
    const float* __restrict__ Wp, const float* __restrict__ bp,
    float* __restrict__ out)
{
    extern __shared__ float sm[];
    float* sR = sm;             // [32][Dd]
    float* sK = sm + 32 * Dd;   // [32][Dd]

    const int tid  = threadIdx.x;
    const int row0 = blockIdx.x * 32;

    for (int i = tid; i < 32 * (Dd / 4); i += 256) {
        int rr = i >> 5;
        int c4 = i & 31;
        int gr = row0 + rr;
        int qi = q[gr];
        ((float4*)(sK + rr * Dd))[c4] = ((const float4*)(Ek + (size_t)qi * Dd))[c4];
        ((float4*)(sR + rr * Dd))[c4] = ((const float4*)(g_read + (size_t)gr * Dd))[c4];
    }
    __syncthreads();

    const int wid = tid >> 5;
    const int cg  = tid & 31;

    u64 ac0[4], ac1[4], ac2[4], ac3[4];
    #pragma unroll
    for (int i = 0; i < 4; i++) { ac0[i]=0ull; ac1[i]=0ull; ac2[i]=0ull; ac3[i]=0ull; }

    for (int j = 0; j < Dd; j += 2) {
        float4 wrA = ((const float4*)(Wf + (size_t)j * Dd))[cg];
        float4 wrB = ((const float4*)(Wf + (size_t)(j + 1) * Dd))[cg];
        float4 wkA = ((const float4*)(Wf + (size_t)(Dd + j) * Dd))[cg];
        float4 wkB = ((const float4*)(Wf + (size_t)(Dd + j + 1) * Dd))[cg];
        u64 wr0 = pack2(wrA.x, wrB.x), wr1 = pack2(wrA.y, wrB.y);
        u64 wr2 = pack2(wrA.z, wrB.z), wr3 = pack2(wrA.w, wrB.w);
        u64 wk0 = pack2(wkA.x, wkB.x), wk1 = pack2(wkA.y, wkB.y);
        u64 wk2 = pack2(wkA.z, wkB.z), wk3 = pack2(wkA.w, wkB.w);
        #pragma unroll
        for (int i = 0; i < 4; i++) {
            u64 rj2 = *(const u64*)(sR + (wid * 4 + i) * Dd + j);
            u64 kj2 = *(const u64*)(sK + (wid * 4 + i) * Dd + j);
            ac0[i] = fma2(rj2, wr0, ac0[i]);
            ac1[i] = fma2(rj2, wr1, ac1[i]);
            ac2[i] = fma2(rj2, wr2, ac2[i]);
            ac3[i] = fma2(rj2, wr3, ac3[i]);
            ac0[i] = fma2(kj2, wk0, ac0[i]);
            ac1[i] = fma2(kj2, wk1, ac1[i]);
            ac2[i] = fma2(kj2, wk2, ac2[i]);
            ac3[i] = fma2(kj2, wk3, ac3[i]);
        }
    }

    float4 bfv = ((const float4*)bf)[cg];
    float4 wp4 = ((const float4*)Wp)[cg];
    float bpv  = bp[0];

    #pragma unroll
    for (int i = 0; i < 4; i++) {
        float fx = tanhf(hsum2(ac0[i]) + bfv.x);
        float fy = tanhf(hsum2(ac1[i]) + bfv.y);
        float fz = tanhf(hsum2(ac2[i]) + bfv.z);
        float fw = tanhf(hsum2(ac3[i]) + bfv.w);
        float pp = fx * wp4.x + fy * wp4.y + fz * wp4.z + fw * wp4.w;
        #pragma unroll
        for (int o = 16; o > 0; o >>= 1)
            pp += __shfl_xor_sync(0xffffffffu, pp, o);
        if (cg == 0)
            out[row0 + wid * 4 + i] = sigmoidf_(pp + bpv);
    }
}

// ---------------------------------------------------------------------------
extern "C" void kernel_launch(void* const* d_in, const int* in_sizes, int n_in,
                              void* d_out, int out_size)
{
    const int*   q   = (const int*)  d_in[0];
    const int*   r   = (const int*)  d_in[1];
    const float* Ek  = (const float*)d_in[2];
    const float* Ev  = (const float*)d_in[3];
    const float* Mk  = (const float*)d_in[4];
    const float* Mv0 = (const float*)d_in[5];
    const float* We  = (const float*)d_in[6];
    const float* be  = (const float*)d_in[7];
    const float* Wa  = (const float*)d_in[8];
    const float* ba  = (const float*)d_in[9];
    const float* Wf  = (const float*)d_in[10];
    const float* bf  = (const float*)d_in[11];
    const float* Wp  = (const float*)d_in[12];
    const float* bp  = (const float*)d_in[13];
    float* out = (float*)d_out;

    const size_t smW  = (size_t)(64 * Dd + (Dd / 2) * Mm * 2) * sizeof(float); // 65536 B
    const size_t smEA = (size_t)(32 * Dd) * sizeof(float);                     // 16384 B
    const size_t smSC = (size_t)(3 * CC * 64) * sizeof(float);                 // 49152 B
    const size_t smP  = (size_t)(2 * 32 * Dd) * sizeof(float);                 // 32768 B
    cudaFuncSetAttribute(k_w,     cudaFuncAttributeMaxDynamicSharedMemorySize, (int)smW);
    cudaFuncSetAttribute(k_ea,    cudaFuncAttributeMaxDynamicSharedMemorySize, (int)smEA);
    cudaFuncSetAttribute(k_scan1, cudaFuncAttributeMaxDynamicSharedMemorySize, (int)smSC);
    cudaFuncSetAttribute(k_scan3, cudaFuncAttributeMaxDynamicSharedMemorySize, (int)smSC);
    cudaFuncSetAttribute(k_post,  cudaFuncAttributeMaxDynamicSharedMemorySize, (int)smP);

    k_w    <<<NROWS / 64, 512, smW>>>(q, Ek, Mk);
    k_ea   <<<NROWS / 32, 256, smEA>>>(q, r, Ev, We, be, Wa, ba);
    k_scan1<<<dim3(Bb, NCH, 2), 256, smSC>>>();
    k_scan2<<<dim3(Bb, 32), 256>>>(Mv0);
    k_scan3<<<dim3(Bb, NCH, 2), 256, smSC>>>();
    k_post <<<NROWS / 32, 256, smP>>>(q, Ek, Wf, bf, Wp, bp, out);
}

// round 10
// speedup vs baseline: 1.2062x; 1.1859x over previous
#include <cuda_runtime.h>
#include <cuda_bf16.h>
#include <cstddef>

// Problem constants
#define NUM_C 1000
#define Dd    128
#define Mm    64
#define Bb    64
#define Ll    512
#define NROWS (Bb * Ll)   // 32768
#define CH    16          // scan: steps staged per chunk

typedef unsigned long long u64;

// Scratch (static device globals — allocation-free)
__device__ float g_w[NROWS * Mm];
__device__ float g_e[NROWS * Dd];
__device__ float g_a[NROWS * Dd];
__device__ float g_read[NROWS * Dd];
// j-pair packed Wf, lane-dense layout:
//   g_WfP[jp*128 + s]: s in [0,64)  -> col = 4*(s>>1) + (s&1)      (pairs (4c,4c+1))
//                      s in [64,128)-> col = 4*((s-64)>>1) + 2 + ((s-64)&1)  (pairs (4c+2,4c+3))
__device__ u64 g_WfP [(Dd / 2) * Dd];
__device__ u64 g_WfkP[(Dd / 2) * Dd];

__device__ __forceinline__ float sigmoidf_(float x) {
    return 1.0f / (1.0f + __expf(-x));
}
__device__ __forceinline__ u64 bcast2(float x) {
    u64 r; asm("mov.b64 %0, {%1,%1};" : "=l"(r) : "f"(x)); return r;
}
__device__ __forceinline__ u64 pack2(float x, float y) {
    u64 r; asm("mov.b64 %0, {%1,%2};" : "=l"(r) : "f"(x), "f"(y)); return r;
}
__device__ __forceinline__ u64 fma2(u64 a, u64 b, u64 c) {
    u64 d; asm("fma.rn.f32x2 %0, %1, %2, %3;" : "=l"(d) : "l"(a), "l"(b), "l"(c)); return d;
}
__device__ __forceinline__ float2 unpk(u64 v) {
    float2 f; asm("mov.b64 {%0,%1}, %2;" : "=f"(f.x), "=f"(f.y) : "l"(v)); return f;
}
__device__ __forceinline__ float hsum2(u64 v) {
    float2 f = unpk(v); return f.x + f.y;
}

// ---------------------------------------------------------------------------
// Kernel 0: repack Wf into j-pair packed, lane-dense layout (both halves).
// ---------------------------------------------------------------------------
__global__ __launch_bounds__(256) void k_prep(const float* __restrict__ Wf)
{
    int idx = blockIdx.x * 256 + threadIdx.x;      // 0 .. 8191
    if (idx < (Dd / 2) * Dd) {
        int jp = idx >> 7;
        int s  = idx & 127;
        int col;
        if (s < 64) col = 4 * (s >> 1) + (s & 1);
        else { int s2 = s - 64; col = 4 * (s2 >> 1) + 2 + (s2 & 1); }
        g_WfP [idx] = pack2(Wf[(size_t)(2 * jp)      * Dd + col],
                            Wf[(size_t)(2 * jp + 1)  * Dd + col]);
        g_WfkP[idx] = pack2(Wf[(size_t)(Dd + 2 * jp)     * Dd + col],
                            Wf[(size_t)(Dd + 2 * jp + 1) * Dd + col]);
    }
}

// ---------------------------------------------------------------------------
// Kernel 1a: logits + softmax -> w.   512 threads, 64 rows/block.
// ---------------------------------------------------------------------------
__global__ __launch_bounds__(512, 2) void k_w(
    const int* __restrict__ q,
    const float* __restrict__ Ek,
    const float* __restrict__ Mk)
{
    extern __shared__ float sm[];
    float* sK   = sm;                 // [64][Dd]  32 KB
    float* sMkP = sm + 64 * Dd;       // [64 jp][64 slots float2]  32 KB

    const int tid  = threadIdx.x;
    const int row0 = blockIdx.x * 64;

    for (int i = tid; i < 64 * (Dd / 4); i += 512) {
        int rr = i >> 5;
        int c4 = i & 31;
        int qi = q[row0 + rr];
        ((float4*)(sK + rr * Dd))[c4] = ((const float4*)(Ek + (size_t)qi * Dd))[c4];
    }
    for (int i = tid; i < Mm * (Dd / 2); i += 512) {
        int s  = i & 63;
        int jp = i >> 6;
        ((float2*)sMkP)[jp * 64 + s] = *(const float2*)(Mk + (size_t)s * Dd + 2 * jp);
    }
    __syncthreads();

    const int wid = tid >> 5;
    const int cg  = tid & 31;

    u64 acc0[4], acc1[4];
    #pragma unroll
    for (int i = 0; i < 4; i++) { acc0[i] = 0ull; acc1[i] = 0ull; }

    for (int jp = 0; jp < Dd / 2; jp++) {
        ulonglong2 mk2 = ((const ulonglong2*)(sMkP + jp * 128))[cg];
        #pragma unroll
        for (int i = 0; i < 4; i++) {
            u64 k2 = *(const u64*)(sK + (wid * 4 + i) * Dd + 2 * jp);
            acc0[i] = fma2(k2, mk2.x, acc0[i]);
            acc1[i] = fma2(k2, mk2.y, acc1[i]);
        }
    }
    #pragma unroll
    for (int i = 0; i < 4; i++) {
        float l0 = hsum2(acc0[i]);
        float l1 = hsum2(acc1[i]);
        float mx = fmaxf(l0, l1);
        #pragma unroll
        for (int o = 16; o > 0; o >>= 1)
            mx = fmaxf(mx, __shfl_xor_sync(0xffffffffu, mx, o));
        float e0 = __expf(l0 - mx);
        float e1 = __expf(l1 - mx);
        float s = e0 + e1;
        #pragma unroll
        for (int o = 16; o > 0; o >>= 1)
            s += __shfl_xor_sync(0xffffffffu, s, o);
        float inv = 1.0f / s;
        *(float2*)(g_w + (size_t)(row0 + wid * 4 + i) * Mm + 2 * cg) =
            make_float2(e0 * inv, e1 * inv);
    }
}

// ---------------------------------------------------------------------------
// Kernel 1b: e = sigmoid(v We + be), a = tanh(v Wa + ba).
// Weights loaded as dense ulonglong2 at [cg] (16B lane stride).
// ---------------------------------------------------------------------------
__global__ __launch_bounds__(256, 4) void k_ea(
    const int* __restrict__ q, const int* __restrict__ r,
    const float* __restrict__ Ev,
    const float* __restrict__ We, const float* __restrict__ be,
    const float* __restrict__ Wa, const float* __restrict__ ba)
{
    extern __shared__ float sm[];
    float* sV = sm;   // [32][Dd]  16 KB

    const int tid  = threadIdx.x;
    const int row0 = blockIdx.x * 32;

    for (int i = tid; i < 32 * (Dd / 4); i += 256) {
        int rr = i >> 5;
        int c4 = i & 31;
        int gr = row0 + rr;
        int xi = q[gr] + NUM_C * r[gr];
        ((float4*)(sV + rr * Dd))[c4] = ((const float4*)(Ev + (size_t)xi * Dd))[c4];
    }
    __syncthreads();

    const int wid = tid >> 5;
    const int cg  = tid & 31;

    u64 eA[4], eB[4], aA[4], aB[4];
    #pragma unroll
    for (int i = 0; i < 4; i++) { eA[i]=0ull; eB[i]=0ull; aA[i]=0ull; aB[i]=0ull; }

    for (int j = 0; j < Dd; j++) {
        ulonglong2 we = __ldg(((const ulonglong2*)(We + (size_t)j * Dd)) + cg);
        ulonglong2 wa = __ldg(((const ulonglong2*)(Wa + (size_t)j * Dd)) + cg);
        #pragma unroll
        for (int i = 0; i < 4; i++) {
            u64 b0 = bcast2(sV[(wid * 4 + i) * Dd + j]);
            eA[i] = fma2(b0, we.x, eA[i]);
            eB[i] = fma2(b0, we.y, eB[i]);
            aA[i] = fma2(b0, wa.x, aA[i]);
            aB[i] = fma2(b0, wa.y, aB[i]);
        }
    }

    float4 bev = ((const float4*)be)[cg];
    float4 bav = ((const float4*)ba)[cg];
    #pragma unroll
    for (int i = 0; i < 4; i++) {
        size_t row = (size_t)(row0 + wid * 4 + i);
        float2 ea = unpk(eA[i]), eb = unpk(eB[i]);
        float2 aa = unpk(aA[i]), ab = unpk(aB[i]);
        float4 ev, av;
        ev.x = sigmoidf_(ea.x + bev.x);
        ev.y = sigmoidf_(ea.y + bev.y);
        ev.z = sigmoidf_(eb.x + bev.z);
        ev.w = sigmoidf_(eb.y + bev.w);
        av.x = tanhf(aa.x + bav.x);
        av.y = tanhf(aa.y + bav.y);
        av.z = tanhf(ab.x + bav.z);
        av.w = tanhf(ab.y + bav.w);
        ((float4*)(g_e + row * Dd))[cg] = ev;
        ((float4*)(g_a + row * Dd))[cg] = av;
    }
}

// ---------------------------------------------------------------------------
// Kernel 2: sequential memory scan. grid (64 batches, 8 d-octants), 256 thr.
// mg = tid&15 owns 4 m-rows; dl = tid>>4 owns one of 16 d-columns.
// ---------------------------------------------------------------------------
__global__ __launch_bounds__(256) void k_scan(const float* __restrict__ Mv0)
{
    const int b    = blockIdx.x;
    const int oct  = blockIdx.y;        // 0..7
    const int tid  = threadIdx.x;
    const int mg   = tid & 15;
    const int dl   = tid >> 4;          // 0..15
    const int d    = oct * 16 + dl;

    float Mv[4];
    #pragma unroll
    for (int i = 0; i < 4; i++)
        Mv[i] = Mv0[(mg * 4 + i) * Dd + d];

    __shared__ float sW[CH][Mm];     // 4 KB
    __shared__ float sE[CH][16];     // 1 KB
    __shared__ float sA[CH][16];     // 1 KB

    const size_t rbase = (size_t)b * Ll;

    for (int c = 0; c < Ll / CH; c++) {
        __syncthreads();
        // stage w: CH*64/4 = 256 float4 — one per thread
        ((float4*)sW)[tid] = ((const float4*)(g_w + (rbase + (size_t)c * CH) * Mm))[tid];
        // stage e,a: 64 float4 each
        if (tid < 64) {
            int tt = tid >> 2, c4 = tid & 3;
            ((float4*)(sE[tt]))[c4] =
                ((const float4*)(g_e + (rbase + (size_t)c * CH + tt) * Dd + oct * 16))[c4];
        } else if (tid < 128) {
            int t2 = tid - 64;
            int tt = t2 >> 2, c4 = t2 & 3;
            ((float4*)(sA[tt]))[c4] =
                ((const float4*)(g_a + (rbase + (size_t)c * CH + tt) * Dd + oct * 16))[c4];
        }
        __syncthreads();

        #pragma unroll 4
        for (int tt = 0; tt < CH; tt++) {
            float ed = sE[tt][dl];
            float ad = sA[tt][dl];
            float rp0 = 0.f, rp1 = 0.f;

            float4 w = ((const float4*)(sW[tt] + mg * 4))[0];

            #define STEP(W, RP, IDX) do {                     \
                RP = fmaf(W, Mv[IDX], RP);                    \
                float t_ = fmaf(Mv[IDX], ed, -ad);            \
                Mv[IDX] = fmaf(-(W), t_, Mv[IDX]);            \
            } while (0)
            STEP(w.x, rp0, 0);  STEP(w.y, rp1, 1);
            STEP(w.z, rp0, 2);  STEP(w.w, rp1, 3);
            #undef STEP

            float rp = rp0 + rp1;
            rp += __shfl_xor_sync(0xffffffffu, rp, 1);
            rp += __shfl_xor_sync(0xffffffffu, rp, 2);
            rp += __shfl_xor_sync(0xffffffffu, rp, 4);
            rp += __shfl_xor_sync(0xffffffffu, rp, 8);
            if (mg == 0)
                g_read[(rbase + (size_t)c * CH + tt) * Dd + d] = rp;
        }
    }
}

// ---------------------------------------------------------------------------
// Kernel 3: f = tanh([read | k] @ Wf + bf); p = sigmoid(f . Wp + bp)
// Pre-packed lane-dense weights: zero packing movs, dense 16B lane stride.
// ---------------------------------------------------------------------------
__global__ __launch_bounds__(256, 4) void k_post(
    const int* __restrict__ q,
    const float* __restrict__ Ek,
    const float* __restrict__ bf,
    const float* __restrict__ Wp, const float* __restrict__ bp,
    float* __restrict__ out)
{
    extern __shared__ float sm[];
    float* sR = sm;             // [32][Dd]
    float* sK = sm + 32 * Dd;   // [32][Dd]

    const int tid  = threadIdx.x;
    const int row0 = blockIdx.x * 32;

    for (int i = tid; i < 32 * (Dd / 4); i += 256) {
        int rr = i >> 5;
        int c4 = i & 31;
        int gr = row0 + rr;
        int qi = q[gr];
        ((float4*)(sK + rr * Dd))[c4] = ((const float4*)(Ek + (size_t)qi * Dd))[c4];
        ((float4*)(sR + rr * Dd))[c4] = ((const float4*)(g_read + (size_t)gr * Dd))[c4];
    }
    __syncthreads();

    const int wid = tid >> 5;
    const int cg  = tid & 31;

    u64 ac0[4], ac1[4], ac2[4], ac3[4];   // cols 4cg..4cg+3, halves over j-parity
    #pragma unroll
    for (int i = 0; i < 4; i++) { ac0[i]=0ull; ac1[i]=0ull; ac2[i]=0ull; ac3[i]=0ull; }

    const u64* wfp  = g_WfP;
    const u64* wfkp = g_WfkP;

    for (int jp = 0; jp < Dd / 2; jp++) {
        ulonglong2 wr01 = __ldg(((const ulonglong2*)(wfp  + jp * Dd))       + cg);
        ulonglong2 wr23 = __ldg(((const ulonglong2*)(wfp  + jp * Dd + 64))  + cg);
        ulonglong2 wk01 = __ldg(((const ulonglong2*)(wfkp + jp * Dd))       + cg);
        ulonglong2 wk23 = __ldg(((const ulonglong2*)(wfkp + jp * Dd + 64))  + cg);
        #pragma unroll
        for (int i = 0; i < 4; i++) {
            u64 rj2 = *(const u64*)(sR + (wid * 4 + i) * Dd + 2 * jp);
            u64 kj2 = *(const u64*)(sK + (wid * 4 + i) * Dd + 2 * jp);
            ac0[i] = fma2(rj2, wr01.x, ac0[i]);
            ac1[i] = fma2(rj2, wr01.y, ac1[i]);
            ac2[i] = fma2(rj2, wr23.x, ac2[i]);
            ac3[i] = fma2(rj2, wr23.y, ac3[i]);
            ac0[i] = fma2(kj2, wk01.x, ac0[i]);
            ac1[i] = fma2(kj2, wk01.y, ac1[i]);
            ac2[i] = fma2(kj2, wk23.x, ac2[i]);
            ac3[i] = fma2(kj2, wk23.y, ac3[i]);
        }
    }

    float4 bfv = ((const float4*)bf)[cg];
    float4 wp4 = ((const float4*)Wp)[cg];
    float bpv  = bp[0];

    #pragma unroll
    for (int i = 0; i < 4; i++) {
        float fx = tanhf(hsum2(ac0[i]) + bfv.x);
        float fy = tanhf(hsum2(ac1[i]) + bfv.y);
        float fz = tanhf(hsum2(ac2[i]) + bfv.z);
        float fw = tanhf(hsum2(ac3[i]) + bfv.w);
        float pp = fx * wp4.x + fy * wp4.y + fz * wp4.z + fw * wp4.w;
        #pragma unroll
        for (int o = 16; o > 0; o >>= 1)
            pp += __shfl_xor_sync(0xffffffffu, pp, o);
        if (cg == 0)
            out[row0 + wid * 4 + i] = sigmoidf_(pp + bpv);
    }
}

// ---------------------------------------------------------------------------
extern "C" void kernel_launch(void* const* d_in, const int* in_sizes, int n_in,
                              void* d_out, int out_size)
{
    const int*   q   = (const int*)  d_in[0];
    const int*   r   = (const int*)  d_in[1];
    const float* Ek  = (const float*)d_in[2];
    const float* Ev  = (const float*)d_in[3];
    const float* Mk  = (const float*)d_in[4];
    const float* Mv0 = (const float*)d_in[5];
    const float* We  = (const float*)d_in[6];
    const float* be  = (const float*)d_in[7];
    const float* Wa  = (const float*)d_in[8];
    const float* ba  = (const float*)d_in[9];
    const float* Wf  = (const float*)d_in[10];
    const float* bf  = (const float*)d_in[11];
    const float* Wp  = (const float*)d_in[12];
    const float* bp  = (const float*)d_in[13];
    float* out = (float*)d_out;

    const size_t smW  = (size_t)(64 * Dd + (Dd / 2) * Mm * 2) * sizeof(float); // 65536 B
    const size_t smEA = (size_t)(32 * Dd) * sizeof(float);                     // 16384 B
    const size_t smP  = (size_t)(2 * 32 * Dd) * sizeof(float);                 // 32768 B
    cudaFuncSetAttribute(k_w,    cudaFuncAttributeMaxDynamicSharedMemorySize, (int)smW);
    cudaFuncSetAttribute(k_ea,   cudaFuncAttributeMaxDynamicSharedMemorySize, (int)smEA);
    cudaFuncSetAttribute(k_post, cudaFuncAttributeMaxDynamicSharedMemorySize, (int)smP);

    k_prep<<<32, 256>>>(Wf);
    k_w   <<<NROWS / 64, 512, smW>>>(q, Ek, Mk);
    k_ea  <<<NROWS / 32, 256, smEA>>>(q, r, Ev, We, be, Wa, ba);
    k_scan<<<dim3(Bb, 8), 256>>>(Mv0);
    k_post<<<NROWS / 32, 256, smP>>>(q, Ek, bf, Wp, bp, out);
}